// round 1
// baseline (speedup 1.0000x reference)
#include <cuda_runtime.h>
#include <cstdint>

// Problem constants (fixed shapes for this problem)
#define K_DIM 4096
#define N_DIM 4096
#define GROUP 128

// GEMM tiling
#define BM 128
#define BN 128
#define BK 32
#define XS_STRIDE 36   // 32 + 4 pad: conflict-free A-fragment LDS
#define WS_STRIDE 132  // 128 + 4 pad: conflict-free B-fragment LDS

// Dequantized weights scratch: [K][N] fp32 (tf32-rounded), 64 MB
__device__ float g_wd[(size_t)K_DIM * N_DIM];

__device__ __forceinline__ float round_tf32(float v) {
    uint32_t r;
    asm("cvt.rna.tf32.f32 %0, %1;" : "=r"(r) : "f"(v));
    return __uint_as_float(r);
}

// ---------------------------------------------------------------------------
// Pass 1: dequantize int4 GPTQ weights -> fp32 (pre-rounded to tf32)
// qweight: [K/8, N] int32 (8 nibbles along K), qzeros: [K/128, N/8] int32,
// scales: [K/128, N].  w[k][n] = (q - (z+1)) * s
// ---------------------------------------------------------------------------
__global__ void dequant_kernel(const int* __restrict__ qweight,
                               const float* __restrict__ scales,
                               const int* __restrict__ qzeros) {
    int idx = blockIdx.x * blockDim.x + threadIdx.x;
    const int total = (K_DIM / 8) * N_DIM;
    if (idx >= total) return;
    int n = idx & (N_DIM - 1);
    int p = idx >> 12;                      // idx / N_DIM
    int packed = qweight[idx];
    int g = p >> 4;                         // (p*8)/128
    float s = scales[g * N_DIM + n];
    int zpacked = qzeros[g * (N_DIM / 8) + (n >> 3)];
    float z = (float)(((zpacked >> ((n & 7) * 4)) & 15) + 1);
#pragma unroll
    for (int i = 0; i < 8; i++) {
        int q = (packed >> (4 * i)) & 15;
        float w = ((float)q - z) * s;
        g_wd[(size_t)(p * 8 + i) * N_DIM + n] = round_tf32(w);
    }
}

// ---------------------------------------------------------------------------
// Pass 2: GEMM  out[M,N] = x[M,K] @ g_wd[K,N] + bias, via mma.sync tf32.
// CTA tile 128x128, K-step 32, 8 warps (4 along M x 2 along N),
// each warp computes 32x64 via m16n8k8 fragments. Double-buffered smem.
// ---------------------------------------------------------------------------
__global__ __launch_bounds__(256) void gemm_tf32_kernel(
    const float* __restrict__ x,
    const float* __restrict__ bias,
    float* __restrict__ out,
    int M) {
    extern __shared__ float smem[];
    float* xs = smem;                             // [2][BM][XS_STRIDE]
    float* ws = smem + 2 * BM * XS_STRIDE;        // [2][BK][WS_STRIDE]

    const int tid = threadIdx.x;
    const int wid = tid >> 5;
    const int lane = tid & 31;
    const int warp_m = (wid & 3) * 32;            // 4 warp-rows of 32
    const int warp_n = (wid >> 2) * 64;           // 2 warp-cols of 64
    const int bm = blockIdx.y * BM;
    const int bn = blockIdx.x * BN;

    float c[2][8][4];
#pragma unroll
    for (int i = 0; i < 2; i++)
#pragma unroll
        for (int j = 0; j < 8; j++)
#pragma unroll
            for (int q = 0; q < 4; q++) c[i][j][q] = 0.0f;

    // Staging addresses (per-thread constants)
    const int x_row = tid >> 3;                   // 0..31 (+32*j)
    const int x_col = (tid & 7) * 4;              // 0..28
    const int w_row = tid >> 5;                   // 0..7 (+8*j)
    const int w_col = lane * 4;                   // 0..124

    float4 xr[4];
    float4 wr[4];

    const int NK = K_DIM / BK;                    // 128

    // -------- prefetch tile 0 --------
#pragma unroll
    for (int j = 0; j < 4; j++) {
        xr[j] = *(const float4*)&x[(size_t)(bm + j * 32 + x_row) * K_DIM + x_col];
        wr[j] = *(const float4*)&g_wd[(size_t)(j * 8 + w_row) * N_DIM + bn + w_col];
    }
    // store tile 0 into buffer 0 (x rounded to tf32 here)
#pragma unroll
    for (int j = 0; j < 4; j++) {
        float4 v = xr[j];
        v.x = round_tf32(v.x); v.y = round_tf32(v.y);
        v.z = round_tf32(v.z); v.w = round_tf32(v.w);
        *(float4*)&xs[(j * 32 + x_row) * XS_STRIDE + x_col] = v;
        *(float4*)&ws[(j * 8 + w_row) * WS_STRIDE + w_col] = wr[j];
    }
    __syncthreads();

    for (int kt = 0; kt < NK; kt++) {
        const bool has_next = (kt + 1) < NK;
        if (has_next) {
            const int knext = (kt + 1) * BK;
#pragma unroll
            for (int j = 0; j < 4; j++) {
                xr[j] = *(const float4*)&x[(size_t)(bm + j * 32 + x_row) * K_DIM + knext + x_col];
                wr[j] = *(const float4*)&g_wd[(size_t)(knext + j * 8 + w_row) * N_DIM + bn + w_col];
            }
        }

        // -------- compute on buffer kt&1 --------
        const float* xb = xs + (kt & 1) * BM * XS_STRIDE;
        const float* wb = ws + (kt & 1) * BK * WS_STRIDE;
#pragma unroll
        for (int ks = 0; ks < 4; ks++) {
            const int k0 = ks * 8 + (lane & 3);
            const int r0 = warp_m + (lane >> 2);
            uint32_t a[2][4];
#pragma unroll
            for (int i = 0; i < 2; i++) {
                a[i][0] = __float_as_uint(xb[(r0 + i * 16) * XS_STRIDE + k0]);
                a[i][1] = __float_as_uint(xb[(r0 + i * 16 + 8) * XS_STRIDE + k0]);
                a[i][2] = __float_as_uint(xb[(r0 + i * 16) * XS_STRIDE + k0 + 4]);
                a[i][3] = __float_as_uint(xb[(r0 + i * 16 + 8) * XS_STRIDE + k0 + 4]);
            }
            uint32_t b[8][2];
#pragma unroll
            for (int j = 0; j < 8; j++) {
                const int cn = warp_n + j * 8 + (lane >> 2);
                b[j][0] = __float_as_uint(wb[k0 * WS_STRIDE + cn]);
                b[j][1] = __float_as_uint(wb[(k0 + 4) * WS_STRIDE + cn]);
            }
#pragma unroll
            for (int i = 0; i < 2; i++) {
#pragma unroll
                for (int j = 0; j < 8; j++) {
                    asm volatile(
                        "mma.sync.aligned.m16n8k8.row.col.f32.tf32.tf32.f32 "
                        "{%0,%1,%2,%3}, {%4,%5,%6,%7}, {%8,%9}, {%0,%1,%2,%3};"
                        : "+f"(c[i][j][0]), "+f"(c[i][j][1]),
                          "+f"(c[i][j][2]), "+f"(c[i][j][3])
                        : "r"(a[i][0]), "r"(a[i][1]), "r"(a[i][2]), "r"(a[i][3]),
                          "r"(b[j][0]), "r"(b[j][1]));
                }
            }
        }

        if (has_next) {
            // write next tile into the other buffer, then one barrier
            float* xn = xs + ((kt + 1) & 1) * BM * XS_STRIDE;
            float* wn = ws + ((kt + 1) & 1) * BK * WS_STRIDE;
#pragma unroll
            for (int j = 0; j < 4; j++) {
                float4 v = xr[j];
                v.x = round_tf32(v.x); v.y = round_tf32(v.y);
                v.z = round_tf32(v.z); v.w = round_tf32(v.w);
                *(float4*)&xn[(j * 32 + x_row) * XS_STRIDE + x_col] = v;
                *(float4*)&wn[(j * 8 + w_row) * WS_STRIDE + w_col] = wr[j];
            }
            __syncthreads();
        }
    }

    // -------- epilogue: add bias, store fp32 --------
#pragma unroll
    for (int i = 0; i < 2; i++) {
#pragma unroll
        for (int j = 0; j < 8; j++) {
            const int row = bm + warp_m + i * 16 + (lane >> 2);
            const int col = bn + warp_n + j * 8 + (lane & 3) * 2;
            const float b0 = bias[col];
            const float b1 = bias[col + 1];
            float2 v0 = make_float2(c[i][j][0] + b0, c[i][j][1] + b1);
            float2 v1 = make_float2(c[i][j][2] + b0, c[i][j][3] + b1);
            *(float2*)&out[(size_t)row * N_DIM + col] = v0;
            *(float2*)&out[(size_t)(row + 8) * N_DIM + col] = v1;
        }
    }
}

// ---------------------------------------------------------------------------
// Launch
// ---------------------------------------------------------------------------
extern "C" void kernel_launch(void* const* d_in, const int* in_sizes, int n_in,
                              void* d_out, int out_size) {
    const float* x       = (const float*)d_in[0];
    const int*   qweight = (const int*)d_in[1];
    const float* scales  = (const float*)d_in[2];
    const int*   qzeros  = (const int*)d_in[3];
    const float* bias    = (const float*)d_in[4];
    float* out = (float*)d_out;

    const int M = in_sizes[0] / K_DIM;   // 8192

    // Pass 1: dequantize weights into scratch
    {
        const int total = (K_DIM / 8) * N_DIM;
        dequant_kernel<<<(total + 255) / 256, 256>>>(qweight, scales, qzeros);
    }

    // Pass 2: GEMM
    {
        const int smem_bytes =
            (2 * BM * XS_STRIDE + 2 * BK * WS_STRIDE) * (int)sizeof(float);
        cudaFuncSetAttribute(gemm_tf32_kernel,
                             cudaFuncAttributeMaxDynamicSharedMemorySize,
                             smem_bytes);
        dim3 grid(N_DIM / BN, M / BM);
        gemm_tf32_kernel<<<grid, 256, smem_bytes>>>(x, bias, out, M);
    }
}

// round 3
// speedup vs baseline: 2.7568x; 2.7568x over previous
#include <cuda_runtime.h>
#include <cuda_fp16.h>
#include <cstdint>

// ---------------------------------------------------------------------------
// Problem constants
// ---------------------------------------------------------------------------
#define K_DIM 4096
#define N_DIM 4096
#define M_MAX 8192

// GEMM tiling
#define BM 256
#define BN 128
#define BKH 64                       // K halfs per stage = 128 bytes per row
#define STAGES 4
#define NT (K_DIM / BKH)             // 64 K-tiles

#define A_TILE_BYTES (BM * BKH * 2)  // 32 KB
#define B_TILE_BYTES (BN * BKH * 2)  // 16 KB
#define STAGE_BYTES  (A_TILE_BYTES + B_TILE_BYTES)   // 48 KB
#define SMEM_TOTAL   (STAGES * STAGE_BYTES)          // 192 KB

// Scratch: W transposed [N][K] fp16, x [M][K] fp16
__device__ __half g_w16[(size_t)N_DIM * K_DIM];
__device__ __half g_x16[(size_t)M_MAX * K_DIM];

// ---------------------------------------------------------------------------
// Helpers
// ---------------------------------------------------------------------------
__device__ __forceinline__ uint32_t smem_u32(const void* p) {
    uint32_t a;
    asm("{ .reg .u64 t; cvta.to.shared.u64 t, %1; cvt.u32.u64 %0, t; }"
        : "=r"(a) : "l"(p));
    return a;
}
__device__ __forceinline__ void cp_async16(uint32_t s, const void* g) {
    asm volatile("cp.async.cg.shared.global [%0], [%1], 16;" :: "r"(s), "l"(g));
}
__device__ __forceinline__ void cp_commit() {
    asm volatile("cp.async.commit_group;" ::: "memory");
}
template <int N>
__device__ __forceinline__ void cp_wait() {
    asm volatile("cp.async.wait_group %0;" :: "n"(N) : "memory");
}
__device__ __forceinline__ void ldsm4(uint32_t& r0, uint32_t& r1, uint32_t& r2,
                                      uint32_t& r3, uint32_t addr) {
    asm volatile("ldmatrix.sync.aligned.m8n8.x4.shared.b16 {%0,%1,%2,%3}, [%4];"
                 : "=r"(r0), "=r"(r1), "=r"(r2), "=r"(r3) : "r"(addr));
}
__device__ __forceinline__ void mma_f16(float& c0, float& c1, float& c2, float& c3,
                                        uint32_t a0, uint32_t a1, uint32_t a2,
                                        uint32_t a3, uint32_t b0, uint32_t b1) {
    asm volatile(
        "mma.sync.aligned.m16n8k16.row.col.f32.f16.f16.f32 "
        "{%0,%1,%2,%3}, {%4,%5,%6,%7}, {%8,%9}, {%0,%1,%2,%3};"
        : "+f"(c0), "+f"(c1), "+f"(c2), "+f"(c3)
        : "r"(a0), "r"(a1), "r"(a2), "r"(a3), "r"(b0), "r"(b1));
}

// ---------------------------------------------------------------------------
// Pass 1: x -> fp16 scratch (8 floats / thread)
// ---------------------------------------------------------------------------
__global__ __launch_bounds__(256) void xhalf_kernel(const float* __restrict__ x) {
    int idx = blockIdx.x * blockDim.x + threadIdx.x;   // [0, M*K/8)
    const float4* x4 = (const float4*)x;
    float4 v0 = x4[2 * idx];
    float4 v1 = x4[2 * idx + 1];
    __half2 h[4];
    h[0] = __floats2half2_rn(v0.x, v0.y);
    h[1] = __floats2half2_rn(v0.z, v0.w);
    h[2] = __floats2half2_rn(v1.x, v1.y);
    h[3] = __floats2half2_rn(v1.z, v1.w);
    *(uint4*)&g_x16[(size_t)idx * 8] = *(uint4*)h;
}

// ---------------------------------------------------------------------------
// Pass 2: dequantize int4 -> fp16, TRANSPOSED to [N][K]
// qweight: [K/8, N], qzeros: [K/128, N/8], scales: [K/128, N]
// ---------------------------------------------------------------------------
__global__ __launch_bounds__(256) void dequant_kernel(const int* __restrict__ qweight,
                                                      const float* __restrict__ scales,
                                                      const int* __restrict__ qzeros) {
    int idx = blockIdx.x * blockDim.x + threadIdx.x;   // [0, N * K/8)
    int p = idx & (K_DIM / 8 - 1);   // packed-k index 0..511
    int n = idx >> 9;
    int packed = qweight[p * N_DIM + n];
    int g = p >> 4;                  // group = (p*8)/128
    float s = scales[g * N_DIM + n];
    int zp = qzeros[g * (N_DIM / 8) + (n >> 3)];
    float z = (float)(((zp >> ((n & 7) * 4)) & 15) + 1);
    __half2 h[4];
#pragma unroll
    for (int i = 0; i < 4; i++) {
        float w0 = ((float)((packed >> (8 * i)) & 15) - z) * s;
        float w1 = ((float)((packed >> (8 * i + 4)) & 15) - z) * s;
        h[i] = __floats2half2_rn(w0, w1);
    }
    *(uint4*)&g_w16[(size_t)n * K_DIM + p * 8] = *(uint4*)h;
}

// ---------------------------------------------------------------------------
// Pass 3: fp16 mma.sync GEMM.  out[M,N] = x16[M,K] @ w16[N,K]^T + bias
// CTA 256x128, BK=64 halfs, 4-stage cp.async, 8 warps of 64x64.
// ---------------------------------------------------------------------------
__device__ __forceinline__ void fill_stage(uint32_t stage_base, const __half* gA,
                                           const __half* gB, int tid) {
    uint32_t sA = stage_base;
    uint32_t sB = stage_base + A_TILE_BYTES;
#pragma unroll
    for (int i = 0; i < 8; i++) {                 // A: 256 rows x 8 chunks
        int c = tid + i * 256;
        int r = c >> 3, cc = c & 7;
        cp_async16(sA + r * 128 + ((cc ^ (r & 7)) << 4), gA + (size_t)r * K_DIM + cc * 8);
    }
#pragma unroll
    for (int i = 0; i < 4; i++) {                 // B: 128 rows x 8 chunks
        int c = tid + i * 256;
        int r = c >> 3, cc = c & 7;
        cp_async16(sB + r * 128 + ((cc ^ (r & 7)) << 4), gB + (size_t)r * K_DIM + cc * 8);
    }
}

__global__ __launch_bounds__(256) void gemm_f16_kernel(const float* __restrict__ bias,
                                                       float* __restrict__ out) {
    extern __shared__ char smem[];
    const uint32_t sbase = smem_u32(smem);
    const int tid = threadIdx.x;
    const int wid = tid >> 5;
    const int lane = tid & 31;
    const int warp_m = (wid & 3) * 64;            // 4 warps along M
    const int warp_n = (wid >> 2) * 64;           // 2 warps along N
    const int bm = blockIdx.y * BM;
    const int bn = blockIdx.x * BN;

    float c[4][8][4];
#pragma unroll
    for (int i = 0; i < 4; i++)
#pragma unroll
        for (int j = 0; j < 8; j++)
#pragma unroll
            for (int q = 0; q < 4; q++) c[i][j][q] = 0.0f;

    const __half* gA0 = &g_x16[(size_t)bm * K_DIM];
    const __half* gB0 = &g_w16[(size_t)bn * K_DIM];

    // ldmatrix per-thread row/chunk bases
    const int a_row = warp_m + (lane & 15);
    const int a_r7 = a_row & 7;
    const int a_chi = lane >> 4;                  // chunk offset 0/1
    const int b_row = warp_n + ((lane >> 4) << 3) + (lane & 7);
    const int b_r7 = b_row & 7;
    const int b_clo = (lane >> 3) & 1;

    // Prologue
#pragma unroll
    for (int t = 0; t < STAGES - 1; t++) {
        fill_stage(sbase + t * STAGE_BYTES, gA0 + t * BKH, gB0 + t * BKH, tid);
        cp_commit();
    }

    for (int t = 0; t < NT; t++) {
        cp_wait<STAGES - 2>();
        __syncthreads();
        const uint32_t sA = sbase + (t & (STAGES - 1)) * STAGE_BYTES;
        const uint32_t sB = sA + A_TILE_BYTES;

#pragma unroll
        for (int s = 0; s < 4; s++) {             // 4 k16-steps per tile
            uint32_t a[4][4];
#pragma unroll
            for (int i = 0; i < 4; i++) {
                int r = a_row + 16 * i;
                uint32_t addr = sA + r * 128 + (((2 * s + a_chi) ^ a_r7) << 4);
                ldsm4(a[i][0], a[i][1], a[i][2], a[i][3], addr);
            }
            uint32_t b[8][2];
#pragma unroll
            for (int jp = 0; jp < 4; jp++) {
                int r = b_row + 16 * jp;
                uint32_t addr = sB + r * 128 + (((2 * s + b_clo) ^ b_r7) << 4);
                ldsm4(b[2 * jp][0], b[2 * jp][1], b[2 * jp + 1][0], b[2 * jp + 1][1], addr);
            }
#pragma unroll
            for (int i = 0; i < 4; i++)
#pragma unroll
                for (int j = 0; j < 8; j++)
                    mma_f16(c[i][j][0], c[i][j][1], c[i][j][2], c[i][j][3],
                            a[i][0], a[i][1], a[i][2], a[i][3], b[j][0], b[j][1]);
        }

        const int f = t + STAGES - 1;
        if (f < NT) {
            fill_stage(sbase + (f & (STAGES - 1)) * STAGE_BYTES,
                       gA0 + f * BKH, gB0 + f * BKH, tid);
        }
        cp_commit();
    }

    // Epilogue: add bias, store fp32
#pragma unroll
    for (int i = 0; i < 4; i++) {
#pragma unroll
        for (int j = 0; j < 8; j++) {
            const int row = bm + warp_m + i * 16 + (lane >> 2);
            const int col = bn + warp_n + j * 8 + (lane & 3) * 2;
            const float b0 = bias[col];
            const float b1 = bias[col + 1];
            *(float2*)&out[(size_t)row * N_DIM + col] =
                make_float2(c[i][j][0] + b0, c[i][j][1] + b1);
            *(float2*)&out[(size_t)(row + 8) * N_DIM + col] =
                make_float2(c[i][j][2] + b0, c[i][j][3] + b1);
        }
    }
}

// ---------------------------------------------------------------------------
// Launch
// ---------------------------------------------------------------------------
extern "C" void kernel_launch(void* const* d_in, const int* in_sizes, int n_in,
                              void* d_out, int out_size) {
    const float* x       = (const float*)d_in[0];
    const int*   qweight = (const int*)d_in[1];
    const float* scales  = (const float*)d_in[2];
    const int*   qzeros  = (const int*)d_in[3];
    const float* bias    = (const float*)d_in[4];
    float* out = (float*)d_out;

    const int M = in_sizes[0] / K_DIM;  // 8192

    // Pass 1: x -> fp16 scratch
    {
        int total8 = (M * K_DIM) / 8;
        xhalf_kernel<<<total8 / 256, 256>>>(x);
    }
    // Pass 2: dequant W -> transposed fp16 scratch
    {
        int total = (K_DIM / 8) * N_DIM;
        dequant_kernel<<<total / 256, 256>>>(qweight, scales, qzeros);
    }
    // Pass 3: GEMM
    {
        cudaFuncSetAttribute(gemm_f16_kernel,
                             cudaFuncAttributeMaxDynamicSharedMemorySize, SMEM_TOTAL);
        dim3 grid(N_DIM / BN, M / BM);
        gemm_f16_kernel<<<grid, 256, SMEM_TOTAL>>>(bias, out);
    }
}

// round 4
// speedup vs baseline: 3.1319x; 1.1361x over previous
#include <cuda_runtime.h>
#include <cuda_fp16.h>
#include <cstdint>

// ---------------------------------------------------------------------------
// Problem constants
// ---------------------------------------------------------------------------
#define K_DIM 4096
#define N_DIM 4096
#define M_MAX 8192

// GEMM tiling: 128x128 CTA tile, 3-stage cp.async pipeline, 2 CTAs/SM
#define BM 128
#define BN 128
#define BKH 64                       // K halfs per stage = 128 bytes per row
#define STAGES 3
#define NT (K_DIM / BKH)             // 64 K-tiles

#define A_TILE_BYTES (BM * BKH * 2)  // 16 KB
#define B_TILE_BYTES (BN * BKH * 2)  // 16 KB
#define STAGE_BYTES  (A_TILE_BYTES + B_TILE_BYTES)   // 32 KB
#define SMEM_TOTAL   (STAGES * STAGE_BYTES)          // 96 KB

// Scratch: W transposed [N][K] fp16, x [M][K] fp16
__device__ __half g_w16[(size_t)N_DIM * K_DIM];
__device__ __half g_x16[(size_t)M_MAX * K_DIM];

// ---------------------------------------------------------------------------
// Helpers
// ---------------------------------------------------------------------------
__device__ __forceinline__ uint32_t smem_u32(const void* p) {
    uint32_t a;
    asm("{ .reg .u64 t; cvta.to.shared.u64 t, %1; cvt.u32.u64 %0, t; }"
        : "=r"(a) : "l"(p));
    return a;
}
__device__ __forceinline__ void cp_async16(uint32_t s, const void* g) {
    asm volatile("cp.async.cg.shared.global [%0], [%1], 16;" :: "r"(s), "l"(g));
}
__device__ __forceinline__ void cp_commit() {
    asm volatile("cp.async.commit_group;" ::: "memory");
}
template <int N>
__device__ __forceinline__ void cp_wait() {
    asm volatile("cp.async.wait_group %0;" :: "n"(N) : "memory");
}
__device__ __forceinline__ void ldsm4(uint32_t& r0, uint32_t& r1, uint32_t& r2,
                                      uint32_t& r3, uint32_t addr) {
    asm volatile("ldmatrix.sync.aligned.m8n8.x4.shared.b16 {%0,%1,%2,%3}, [%4];"
                 : "=r"(r0), "=r"(r1), "=r"(r2), "=r"(r3) : "r"(addr));
}
__device__ __forceinline__ void mma_f16(float& c0, float& c1, float& c2, float& c3,
                                        uint32_t a0, uint32_t a1, uint32_t a2,
                                        uint32_t a3, uint32_t b0, uint32_t b1) {
    asm volatile(
        "mma.sync.aligned.m16n8k16.row.col.f32.f16.f16.f32 "
        "{%0,%1,%2,%3}, {%4,%5,%6,%7}, {%8,%9}, {%0,%1,%2,%3};"
        : "+f"(c0), "+f"(c1), "+f"(c2), "+f"(c3)
        : "r"(a0), "r"(a1), "r"(a2), "r"(a3), "r"(b0), "r"(b1));
}

// ---------------------------------------------------------------------------
// Pass 1: x -> fp16 scratch (8 floats / thread)
// ---------------------------------------------------------------------------
__global__ __launch_bounds__(256) void xhalf_kernel(const float* __restrict__ x) {
    int idx = blockIdx.x * blockDim.x + threadIdx.x;   // [0, M*K/8)
    const float4* x4 = (const float4*)x;
    float4 v0 = x4[2 * idx];
    float4 v1 = x4[2 * idx + 1];
    __half2 h[4];
    h[0] = __floats2half2_rn(v0.x, v0.y);
    h[1] = __floats2half2_rn(v0.z, v0.w);
    h[2] = __floats2half2_rn(v1.x, v1.y);
    h[3] = __floats2half2_rn(v1.z, v1.w);
    *(uint4*)&g_x16[(size_t)idx * 8] = *(uint4*)h;
}

// ---------------------------------------------------------------------------
// Pass 2: dequantize int4 -> fp16, TRANSPOSED to [N][K]
// qweight: [K/8, N], qzeros: [K/128, N/8], scales: [K/128, N]
// ---------------------------------------------------------------------------
__global__ __launch_bounds__(256) void dequant_kernel(const int* __restrict__ qweight,
                                                      const float* __restrict__ scales,
                                                      const int* __restrict__ qzeros) {
    int idx = blockIdx.x * blockDim.x + threadIdx.x;   // [0, N * K/8)
    int p = idx & (K_DIM / 8 - 1);   // packed-k index 0..511
    int n = idx >> 9;
    int packed = qweight[p * N_DIM + n];
    int g = p >> 4;                  // group = (p*8)/128
    float s = scales[g * N_DIM + n];
    int zp = qzeros[g * (N_DIM / 8) + (n >> 3)];
    float z = (float)(((zp >> ((n & 7) * 4)) & 15) + 1);
    __half2 h[4];
#pragma unroll
    for (int i = 0; i < 4; i++) {
        float w0 = ((float)((packed >> (8 * i)) & 15) - z) * s;
        float w1 = ((float)((packed >> (8 * i + 4)) & 15) - z) * s;
        h[i] = __floats2half2_rn(w0, w1);
    }
    *(uint4*)&g_w16[(size_t)n * K_DIM + p * 8] = *(uint4*)h;
}

// ---------------------------------------------------------------------------
// Pass 3: fp16 mma.sync GEMM.  out[M,N] = x16[M,K] @ w16[N,K]^T + bias
// CTA 128x128, BKH=64, 3-stage cp.async, 8 warps of 32x64, 2 CTAs/SM.
// ---------------------------------------------------------------------------
__device__ __forceinline__ void fill_stage(uint32_t stage_base, const __half* gA,
                                           const __half* gB, int tid) {
    uint32_t sA = stage_base;
    uint32_t sB = stage_base + A_TILE_BYTES;
#pragma unroll
    for (int i = 0; i < 4; i++) {                 // A: 128 rows x 8 chunks
        int c = tid + i * 256;
        int r = c >> 3, cc = c & 7;
        cp_async16(sA + r * 128 + ((cc ^ (r & 7)) << 4), gA + (size_t)r * K_DIM + cc * 8);
    }
#pragma unroll
    for (int i = 0; i < 4; i++) {                 // B: 128 rows x 8 chunks
        int c = tid + i * 256;
        int r = c >> 3, cc = c & 7;
        cp_async16(sB + r * 128 + ((cc ^ (r & 7)) << 4), gB + (size_t)r * K_DIM + cc * 8);
    }
}

__global__ __launch_bounds__(256, 2) void gemm_f16_kernel(const float* __restrict__ bias,
                                                          float* __restrict__ out) {
    extern __shared__ char smem[];
    const uint32_t sbase = smem_u32(smem);
    const int tid = threadIdx.x;
    const int wid = tid >> 5;
    const int lane = tid & 31;
    const int warp_m = (wid & 3) * 32;            // 4 warps along M (32 rows each)
    const int warp_n = (wid >> 2) * 64;           // 2 warps along N (64 cols each)
    const int bm = blockIdx.y * BM;
    const int bn = blockIdx.x * BN;

    float c[2][8][4];
#pragma unroll
    for (int i = 0; i < 2; i++)
#pragma unroll
        for (int j = 0; j < 8; j++)
#pragma unroll
            for (int q = 0; q < 4; q++) c[i][j][q] = 0.0f;

    const __half* gA0 = &g_x16[(size_t)bm * K_DIM];
    const __half* gB0 = &g_w16[(size_t)bn * K_DIM];

    // ldmatrix per-thread row/chunk bases
    const int a_row = warp_m + (lane & 15);
    const int a_r7 = a_row & 7;
    const int a_chi = lane >> 4;                  // chunk offset 0/1
    const int b_row = warp_n + ((lane >> 4) << 3) + (lane & 7);
    const int b_r7 = b_row & 7;
    const int b_clo = (lane >> 3) & 1;

    // Prologue: fill stages 0..STAGES-2
#pragma unroll
    for (int t = 0; t < STAGES - 1; t++) {
        fill_stage(sbase + t * STAGE_BYTES, gA0 + t * BKH, gB0 + t * BKH, tid);
        cp_commit();
    }

    int slot = 0;
    for (int t = 0; t < NT; t++) {
        cp_wait<STAGES - 2>();
        __syncthreads();
        const uint32_t sA = sbase + slot * STAGE_BYTES;
        const uint32_t sB = sA + A_TILE_BYTES;

#pragma unroll
        for (int s = 0; s < 4; s++) {             // 4 k16-steps per tile
            uint32_t a[2][4];
#pragma unroll
            for (int i = 0; i < 2; i++) {
                int r = a_row + 16 * i;
                uint32_t addr = sA + r * 128 + (((2 * s + a_chi) ^ a_r7) << 4);
                ldsm4(a[i][0], a[i][1], a[i][2], a[i][3], addr);
            }
            uint32_t b[8][2];
#pragma unroll
            for (int jp = 0; jp < 4; jp++) {
                int r = b_row + 16 * jp;
                uint32_t addr = sB + r * 128 + (((2 * s + b_clo) ^ b_r7) << 4);
                ldsm4(b[2 * jp][0], b[2 * jp][1], b[2 * jp + 1][0], b[2 * jp + 1][1], addr);
            }
#pragma unroll
            for (int i = 0; i < 2; i++)
#pragma unroll
                for (int j = 0; j < 8; j++)
                    mma_f16(c[i][j][0], c[i][j][1], c[i][j][2], c[i][j][3],
                            a[i][0], a[i][1], a[i][2], a[i][3], b[j][0], b[j][1]);
        }

        const int f = t + STAGES - 1;
        if (f < NT) {
            int fslot = slot + (STAGES - 1); if (fslot >= STAGES) fslot -= STAGES;
            fill_stage(sbase + fslot * STAGE_BYTES,
                       gA0 + (size_t)f * BKH, gB0 + (size_t)f * BKH, tid);
        }
        cp_commit();
        if (++slot == STAGES) slot = 0;
    }

    // Epilogue: add bias, store fp32
#pragma unroll
    for (int i = 0; i < 2; i++) {
#pragma unroll
        for (int j = 0; j < 8; j++) {
            const int row = bm + warp_m + i * 16 + (lane >> 2);
            const int col = bn + warp_n + j * 8 + (lane & 3) * 2;
            const float b0 = bias[col];
            const float b1 = bias[col + 1];
            *(float2*)&out[(size_t)row * N_DIM + col] =
                make_float2(c[i][j][0] + b0, c[i][j][1] + b1);
            *(float2*)&out[(size_t)(row + 8) * N_DIM + col] =
                make_float2(c[i][j][2] + b0, c[i][j][3] + b1);
        }
    }
}

// ---------------------------------------------------------------------------
// Launch
// ---------------------------------------------------------------------------
extern "C" void kernel_launch(void* const* d_in, const int* in_sizes, int n_in,
                              void* d_out, int out_size) {
    const float* x       = (const float*)d_in[0];
    const int*   qweight = (const int*)d_in[1];
    const float* scales  = (const float*)d_in[2];
    const int*   qzeros  = (const int*)d_in[3];
    const float* bias    = (const float*)d_in[4];
    float* out = (float*)d_out;

    const int M = in_sizes[0] / K_DIM;  // 8192

    // Pass 1: x -> fp16 scratch
    {
        int total8 = (M * K_DIM) / 8;
        xhalf_kernel<<<total8 / 256, 256>>>(x);
    }
    // Pass 2: dequant W -> transposed fp16 scratch
    {
        int total = (K_DIM / 8) * N_DIM;
        dequant_kernel<<<total / 256, 256>>>(qweight, scales, qzeros);
    }
    // Pass 3: GEMM
    {
        cudaFuncSetAttribute(gemm_f16_kernel,
                             cudaFuncAttributeMaxDynamicSharedMemorySize, SMEM_TOTAL);
        dim3 grid(N_DIM / BN, M / BM);
        gemm_f16_kernel<<<grid, 256, SMEM_TOTAL>>>(bias, out);
    }
}